// round 14
// baseline (speedup 1.0000x reference)
#include <cuda_runtime.h>
#include <math.h>
#include <stdint.h>

#define D 32
#define NCOL 529          // 1 + 32 + 496
#define LOG2E 1.4426950408889634f
#define TRAIN_BLOCKS 592

// ---- scratch (no allocations allowed) ----
__device__ float  g_acc[560];    // [0..527] upper-tri X^T X (incl diag), [528..559] column sums
__device__ float  g_stats[64];   // mean[32], inv_sd[32]
__device__ float4 g_pc[512];     // circulant order: entry k*32+lane = pair (lane,(lane+k+1)&31)

__device__ __forceinline__ int tri_idx(int i, int j) {   // i <= j, upper triangle incl diag
    return i * 32 - (i * (i - 1)) / 2 + (j - i);
}

__device__ __forceinline__ float ex2f(float v) {
    float r;
    asm("ex2.approx.ftz.f32 %0, %1;" : "=f"(r) : "f"(v));
    return r;
}

__device__ __forceinline__ uint32_t smem_u32(const void* p) {
    uint32_t a;
    asm("{ .reg .u64 t; cvta.to.shared.u64 t, %1; cvt.u32.u64 %0, t; }" : "=r"(a) : "l"(p));
    return a;
}

// ---------------- kernel 0: zero accumulators (graph replays must be deterministic) ----------
__global__ void zero_kernel() {
    int t = blockIdx.x * blockDim.x + threadIdx.x;
    if (t < 560) g_acc[t] = 0.0f;
}

// ---------------- kernel 1: circulant-shuffle SYRK (r9 proven version) -----------------------
__global__ void __launch_bounds__(256) train_kernel(const float* __restrict__ X, int n_train) {
    __shared__ float sacc[560];
    const int tid  = threadIdx.x;
    const int lane = tid & 31;
    const int wg   = blockIdx.x * 8 + (tid >> 5);      // global warp id
    const int W    = gridDim.x * 8;

    for (int t = tid; t < 560; t += 256) sacc[t] = 0.0f;

    float acc[17];
#pragma unroll
    for (int k = 0; k < 17; k++) acc[k] = 0.0f;
    float asum = 0.0f;

    int row = wg;
    for (; row + 3 * W < n_train; row += 4 * W) {       // MLP=4 batched loads
        float v0 = X[(size_t)row * 32 + lane];
        float v1 = X[(size_t)(row + W) * 32 + lane];
        float v2 = X[(size_t)(row + 2 * W) * 32 + lane];
        float v3 = X[(size_t)(row + 3 * W) * 32 + lane];
        asum += (v0 + v1) + (v2 + v3);
#pragma unroll
        for (int k = 0; k < 17; k++) {
            int src = (lane + k) & 31;
            acc[k] = fmaf(v0, __shfl_sync(0xffffffffu, v0, src), acc[k]);
            acc[k] = fmaf(v1, __shfl_sync(0xffffffffu, v1, src), acc[k]);
            acc[k] = fmaf(v2, __shfl_sync(0xffffffffu, v2, src), acc[k]);
            acc[k] = fmaf(v3, __shfl_sync(0xffffffffu, v3, src), acc[k]);
        }
    }
    for (; row < n_train; row += W) {                   // warp-uniform tail
        float v = X[(size_t)row * 32 + lane];
        asum += v;
#pragma unroll
        for (int k = 0; k < 17; k++)
            acc[k] = fmaf(v, __shfl_sync(0xffffffffu, v, (lane + k) & 31), acc[k]);
    }
    __syncthreads();   // sacc zeroed before smem atomics

#pragma unroll
    for (int k = 0; k < 17; k++) {
        int i = lane, j = (lane + k) & 31;
        int lo = min(i, j), hi = max(i, j);
        if (k < 16 || lane < 16)                        // k=16 pairs duplicated across half-warps
            atomicAdd(&sacc[tri_idx(lo, hi)], acc[k]);
    }
    atomicAdd(&sacc[528 + lane], asum);
    __syncthreads();

    for (int t = tid; t < 560; t += 256)                // spread-address global atomics
        atomicAdd(&g_acc[t], sacc[t]);
}

// ---------------- kernel 2: stats + circulant pair-constant table (1 block) ------------------
__global__ void __launch_bounds__(512) prep_kernel(int n_train) {
    __shared__ float mean_s[32], isd_s[32];
    const int t   = threadIdx.x;
    const float fn = (float)n_train;

    if (t < 32) {
        float m   = g_acc[528 + t] / fn;
        float var = (g_acc[tri_idx(t, t)] - fn * m * m) / (fn - 1.0f);
        float isd = 1.0f / sqrtf(var);
        mean_s[t] = m;  isd_s[t] = isd;
        g_stats[t] = m; g_stats[32 + t] = isd;
    }
    __syncthreads();

    // circulant entry: k = t>>5 (offset d = k+1), lane = t&31 -> pair (lane, (lane+d)&31)
    int k = t >> 5, lane = t & 31, d = k + 1;
    int a = lane, b = (lane + d) & 31;
    int i = min(a, b), j = max(a, b);
    bool valid = (d < 16) || (lane < 16);    // d=16 second half duplicates

    float4 pc;
    if (valid) {
        float cij = (g_acc[tri_idx(i, j)] - fn * mean_s[i] * mean_s[j]) / (fn - 1.0f);
        float r   = cij * isd_s[i] * isd_s[j];
        float om  = 1.0f - r * r;
        float inv = 1.0f / om;
        pc.x = 0.5f * r * r * inv * LOG2E;      // A' (coeff of zi^2+zj^2, base 2)
        pc.y = -r * inv * LOG2E;                // B' (coeff of zi*zj, base 2)
        pc.z = 0.5f * log2f(om);                // D' = log2(sqrt(1-r^2))
        int p   = 31 * i - (i * (i - 1)) / 2 + (j - i - 1);   // combinations() pair index
        pc.w = __int_as_float(33 + p);          // output column
    } else {
        pc.x = pc.y = pc.z = 0.0f;
        pc.w = __int_as_float(-1);
    }
    g_pc[t] = pc;
}

// ---------------- kernel 3: eval — 2 points/warp, warp-pair shared 4-point tile --------------
// smem/block ~25.4KB -> 8-9 blocks/SM (~32-36 warps, ~50% occ) vs 20 warps before.
__global__ void __launch_bounds__(128) eval_kernel(const float* __restrict__ x,
                                                   float* __restrict__ out, int n_eval) {
    __shared__ float4 pc[512];
    __shared__ float  st[64];
    __shared__ __align__(16) float buf[2 * 4 * NCOL];   // 2 warp-pairs x (4 points x 529)
    const int tid = threadIdx.x;
    pc[tid]       = g_pc[tid];
    pc[tid + 128] = g_pc[tid + 128];
    pc[tid + 256] = g_pc[tid + 256];
    pc[tid + 384] = g_pc[tid + 384];
    if (tid < 64) st[tid] = g_stats[tid];
    __syncthreads();

    const int lane = tid & 31;
    const int w    = tid >> 5;
    const int pair = w >> 1;                            // 0..1
    const int half = w & 1;                             // which 2 points of the tile
    const int tile0 = (blockIdx.x * 2 + pair) * 4;      // tile = 4 points, shared by warp pair
    if (tile0 >= n_eval) return;                        // pair-uniform exit
    const int vtile = min(4, n_eval - tile0);
    const int p0    = tile0 + half * 2;                 // this warp's 2 points

    float* tb = buf + pair * (4 * NCOL);                // pair tile buffer
    float* wb = tb + half * (2 * NCOL);                 // this warp's half

    const float mean = st[lane], isd = st[32 + lane];
    int i0 = min(p0,     n_eval - 1);
    int i1 = min(p0 + 1, n_eval - 1);
    float z0 = (x[(size_t)i0 * 32 + lane] - mean) * isd;
    float z1 = (x[(size_t)i1 * 32 + lane] - mean) * isd;
    float q0 = z0 * z0, q1 = z1 * z1;

    // ones: cols 0..32 for each of this warp's points
    wb[lane] = 1.0f; wb[NCOL + lane] = 1.0f;
    if (lane == 0) { wb[32] = 1.0f; wb[NCOL + 32] = 1.0f; }

#pragma unroll
    for (int k = 0; k < 16; k++) {
        float4 c  = pc[k * 32 + lane];
        int   col = __float_as_int(c.w);                // -1 = masked duplicate (d=16 upper half)
        int   src = (lane + k + 1) & 31;

        float zj0 = __shfl_sync(0xffffffffu, z0, src);
        float zj1 = __shfl_sync(0xffffffffu, z1, src);

        float v0 = ex2f(fmaf(c.x, fmaf(zj0, zj0, q0), fmaf(c.y, z0 * zj0, c.z)));
        float v1 = ex2f(fmaf(c.x, fmaf(zj1, zj1, q1), fmaf(c.y, z1 * zj1, c.z)));

        if (col >= 0) {
            wb[col]        = v0;
            wb[NCOL + col] = v1;
        }
    }

    // pair barrier: both warps' halves staged (named barriers 1,2; 64 threads each)
    asm volatile("bar.sync %0, %1;" :: "r"(pair + 1), "r"(64) : "memory");

    if (vtile == 4) {
        if (half == 0 && lane == 0) {
            asm volatile("fence.proxy.async.shared::cta;" ::: "memory");
            float* gdst = out + (size_t)tile0 * NCOL;       // tile0 % 4 == 0 -> 16B aligned
            uint32_t ssrc = smem_u32(tb);                   // 8464B block, 16B aligned
            asm volatile("cp.async.bulk.global.shared::cta.bulk_group [%0], [%1], %2;"
                         :: "l"(gdst), "r"(ssrc), "r"(4 * NCOL * 4) : "memory");
            asm volatile("cp.async.bulk.commit_group;" ::: "memory");
            asm volatile("cp.async.bulk.wait_group 0;" ::: "memory");
        }
    } else {
        int myv = min(2, max(0, n_eval - p0));              // rare tail: scalar copy of my half
        int n   = myv * NCOL;
        for (int e = lane; e < n; e += 32)
            out[(size_t)p0 * NCOL + e] = wb[e];
    }
}

// ---------------- launcher ----------------
extern "C" void kernel_launch(void* const* d_in, const int* in_sizes, int n_in,
                              void* d_out, int out_size) {
    const float* X_train = (const float*)d_in[0];
    const float* x       = (const float*)d_in[1];
    float*       out     = (float*)d_out;

    int n_train = in_sizes[0] / D;
    int n_eval  = in_sizes[1] / D;

    zero_kernel<<<3, 256>>>();
    train_kernel<<<TRAIN_BLOCKS, 256>>>(X_train, n_train);
    prep_kernel<<<1, 512>>>(n_train);

    int tiles  = (n_eval + 3) / 4;            // 4-point tiles, one per warp-pair
    int blocks = (tiles + 1) / 2;             // 2 pairs per 128-thread block
    eval_kernel<<<blocks, 128>>>(x, out, n_eval);
}

// round 15
// speedup vs baseline: 1.4289x; 1.4289x over previous
#include <cuda_runtime.h>
#include <math.h>
#include <stdint.h>

#define D 32
#define NCOL 529          // 1 + 32 + 496
#define LOG2E 1.4426950408889634f
#define TRAIN_BLOCKS 592

// ---- scratch (no allocations allowed) ----
__device__ float  g_acc[560];    // [0..527] upper-tri X^T X (incl diag), [528..559] column sums
__device__ float  g_stats[64];   // mean[32], inv_sd[32]
__device__ float4 g_pc[512];     // circulant order: entry k*32+lane = pair (lane,(lane+k+1)&31)

__device__ __forceinline__ int tri_idx(int i, int j) {   // i <= j, upper triangle incl diag
    return i * 32 - (i * (i - 1)) / 2 + (j - i);
}

__device__ __forceinline__ float ex2f(float v) {
    float r;
    asm("ex2.approx.ftz.f32 %0, %1;" : "=f"(r) : "f"(v));
    return r;
}

__device__ __forceinline__ uint32_t smem_u32(const void* p) {
    uint32_t a;
    asm("{ .reg .u64 t; cvta.to.shared.u64 t, %1; cvt.u32.u64 %0, t; }" : "=r"(a) : "l"(p));
    return a;
}

// ---------------- kernel 0: zero accumulators (graph replays must be deterministic) ----------
__global__ void zero_kernel() {
    int t = blockIdx.x * blockDim.x + threadIdx.x;
    if (t < 560) g_acc[t] = 0.0f;
}

// ---------------- kernel 1: circulant-shuffle SYRK (r9 proven version) -----------------------
__global__ void __launch_bounds__(256) train_kernel(const float* __restrict__ X, int n_train) {
    __shared__ float sacc[560];
    const int tid  = threadIdx.x;
    const int lane = tid & 31;
    const int wg   = blockIdx.x * 8 + (tid >> 5);      // global warp id
    const int W    = gridDim.x * 8;

    for (int t = tid; t < 560; t += 256) sacc[t] = 0.0f;

    float acc[17];
#pragma unroll
    for (int k = 0; k < 17; k++) acc[k] = 0.0f;
    float asum = 0.0f;

    int row = wg;
    for (; row + 3 * W < n_train; row += 4 * W) {       // MLP=4 batched loads
        float v0 = X[(size_t)row * 32 + lane];
        float v1 = X[(size_t)(row + W) * 32 + lane];
        float v2 = X[(size_t)(row + 2 * W) * 32 + lane];
        float v3 = X[(size_t)(row + 3 * W) * 32 + lane];
        asum += (v0 + v1) + (v2 + v3);
#pragma unroll
        for (int k = 0; k < 17; k++) {
            int src = (lane + k) & 31;
            acc[k] = fmaf(v0, __shfl_sync(0xffffffffu, v0, src), acc[k]);
            acc[k] = fmaf(v1, __shfl_sync(0xffffffffu, v1, src), acc[k]);
            acc[k] = fmaf(v2, __shfl_sync(0xffffffffu, v2, src), acc[k]);
            acc[k] = fmaf(v3, __shfl_sync(0xffffffffu, v3, src), acc[k]);
        }
    }
    for (; row < n_train; row += W) {                   // warp-uniform tail
        float v = X[(size_t)row * 32 + lane];
        asum += v;
#pragma unroll
        for (int k = 0; k < 17; k++)
            acc[k] = fmaf(v, __shfl_sync(0xffffffffu, v, (lane + k) & 31), acc[k]);
    }
    __syncthreads();   // sacc zeroed before smem atomics

#pragma unroll
    for (int k = 0; k < 17; k++) {
        int i = lane, j = (lane + k) & 31;
        int lo = min(i, j), hi = max(i, j);
        if (k < 16 || lane < 16)                        // k=16 pairs duplicated across half-warps
            atomicAdd(&sacc[tri_idx(lo, hi)], acc[k]);
    }
    atomicAdd(&sacc[528 + lane], asum);
    __syncthreads();

    for (int t = tid; t < 560; t += 256)                // spread-address global atomics
        atomicAdd(&g_acc[t], sacc[t]);
}

// ---------------- kernel 2: stats + circulant pair-constant table (1 block) ------------------
__global__ void __launch_bounds__(512) prep_kernel(int n_train) {
    __shared__ float mean_s[32], isd_s[32];
    const int t   = threadIdx.x;
    const float fn = (float)n_train;

    if (t < 32) {
        float m   = g_acc[528 + t] / fn;
        float var = (g_acc[tri_idx(t, t)] - fn * m * m) / (fn - 1.0f);
        float isd = 1.0f / sqrtf(var);
        mean_s[t] = m;  isd_s[t] = isd;
        g_stats[t] = m; g_stats[32 + t] = isd;
    }
    __syncthreads();

    // circulant entry: k = t>>5 (offset d = k+1), lane = t&31 -> pair (lane, (lane+d)&31)
    int k = t >> 5, lane = t & 31, d = k + 1;
    int a = lane, b = (lane + d) & 31;
    int i = min(a, b), j = max(a, b);
    bool valid = (d < 16) || (lane < 16);    // d=16 second half duplicates

    float4 pc;
    if (valid) {
        float cij = (g_acc[tri_idx(i, j)] - fn * mean_s[i] * mean_s[j]) / (fn - 1.0f);
        float r   = cij * isd_s[i] * isd_s[j];
        float om  = 1.0f - r * r;
        float inv = 1.0f / om;
        pc.x = 0.5f * r * r * inv * LOG2E;      // A' (coeff of zi^2+zj^2, base 2)
        pc.y = -r * inv * LOG2E;                // B' (coeff of zi*zj, base 2)
        pc.z = 0.5f * log2f(om);                // D' = log2(sqrt(1-r^2))
        int p   = 31 * i - (i * (i - 1)) / 2 + (j - i - 1);   // combinations() pair index
        pc.w = __int_as_float(33 + p);          // output column
    } else {
        pc.x = pc.y = pc.z = 0.0f;
        pc.w = __int_as_float(-1);
    }
    g_pc[t] = pc;
}

// ---------------- kernel 3: eval — r9 shape; pc/stats via L1-broadcast LDG (no smem table) ---
// smem/block = 33.9KB (4 store buffers only) -> 6 blocks/SM = 24 warps vs r9's 20.
__global__ void __launch_bounds__(128) eval_kernel(const float* __restrict__ x,
                                                   float* __restrict__ out, int n_eval) {
    __shared__ __align__(16) float buf[4 * 4 * NCOL];   // 4 warps x (4 points x 529)

    const int tid  = threadIdx.x;
    const int lane = tid & 31;
    const int w    = tid >> 5;
    const int p0   = (blockIdx.x * 4 + w) * 4;           // 4 points per warp
    if (p0 >= n_eval) return;                             // warp-uniform; no block syncs anywhere
    const int valid = min(4, n_eval - p0);

    float* wb = buf + w * (4 * NCOL);

    const float mean = __ldg(&g_stats[lane]);
    const float isd  = __ldg(&g_stats[32 + lane]);
    // clamp reads for (rare) tail points
    int i0 = p0, i1 = min(p0 + 1, n_eval - 1), i2 = min(p0 + 2, n_eval - 1), i3 = min(p0 + 3, n_eval - 1);
    float z0 = (x[(size_t)i0 * 32 + lane] - mean) * isd;
    float z1 = (x[(size_t)i1 * 32 + lane] - mean) * isd;
    float z2 = (x[(size_t)i2 * 32 + lane] - mean) * isd;
    float z3 = (x[(size_t)i3 * 32 + lane] - mean) * isd;
    float q0 = z0 * z0, q1 = z1 * z1, q2 = z2 * z2, q3 = z3 * z3;

    // ones: cols 0..32 for each point
    wb[lane] = 1.0f; wb[NCOL + lane] = 1.0f; wb[2 * NCOL + lane] = 1.0f; wb[3 * NCOL + lane] = 1.0f;
    if (lane == 0) {
        wb[32] = 1.0f; wb[NCOL + 32] = 1.0f; wb[2 * NCOL + 32] = 1.0f; wb[3 * NCOL + 32] = 1.0f;
    }

#pragma unroll
    for (int k = 0; k < 16; k++) {
        float4 c  = __ldg(&g_pc[k * 32 + lane]);         // L1-broadcast hit: warp-uniform k
        int   col = __float_as_int(c.w);                 // -1 = masked duplicate (d=16 upper half)
        int   src = (lane + k + 1) & 31;

        float zj0 = __shfl_sync(0xffffffffu, z0, src);
        float zj1 = __shfl_sync(0xffffffffu, z1, src);
        float zj2 = __shfl_sync(0xffffffffu, z2, src);
        float zj3 = __shfl_sync(0xffffffffu, z3, src);

        float v0 = ex2f(fmaf(c.x, fmaf(zj0, zj0, q0), fmaf(c.y, z0 * zj0, c.z)));
        float v1 = ex2f(fmaf(c.x, fmaf(zj1, zj1, q1), fmaf(c.y, z1 * zj1, c.z)));
        float v2 = ex2f(fmaf(c.x, fmaf(zj2, zj2, q2), fmaf(c.y, z2 * zj2, c.z)));
        float v3 = ex2f(fmaf(c.x, fmaf(zj3, zj3, q3), fmaf(c.y, z3 * zj3, c.z)));

        if (col >= 0) {
            wb[col]            = v0;
            wb[NCOL + col]     = v1;
            wb[2 * NCOL + col] = v2;
            wb[3 * NCOL + col] = v3;
        }
    }

    __syncwarp();

    if (valid == 4) {
        if (lane == 0) {
            asm volatile("fence.proxy.async.shared::cta;" ::: "memory");
            float* gdst = out + (size_t)p0 * NCOL;           // p0 % 4 == 0 -> 16B aligned
            uint32_t ssrc = smem_u32(wb);                    // 8464B block, 16B aligned
            asm volatile("cp.async.bulk.global.shared::cta.bulk_group [%0], [%1], %2;"
                         :: "l"(gdst), "r"(ssrc), "r"(4 * NCOL * 4) : "memory");
            asm volatile("cp.async.bulk.commit_group;" ::: "memory");
            asm volatile("cp.async.bulk.wait_group 0;" ::: "memory");
        }
    } else {
        int n = valid * NCOL;                                // rare tail: scalar copy
        for (int e = lane; e < n; e += 32)
            out[(size_t)p0 * NCOL + e] = wb[e];
    }
}

// ---------------- launcher ----------------
extern "C" void kernel_launch(void* const* d_in, const int* in_sizes, int n_in,
                              void* d_out, int out_size) {
    const float* X_train = (const float*)d_in[0];
    const float* x       = (const float*)d_in[1];
    float*       out     = (float*)d_out;

    int n_train = in_sizes[0] / D;
    int n_eval  = in_sizes[1] / D;

    zero_kernel<<<3, 256>>>();
    train_kernel<<<TRAIN_BLOCKS, 256>>>(X_train, n_train);
    prep_kernel<<<1, 512>>>(n_train);

    int warps  = (n_eval + 3) / 4;            // 4 points per warp
    int blocks = (warps + 3) / 4;             // 4 warps per block
    eval_kernel<<<blocks, 128>>>(x, out, n_eval);
}

// round 16
// speedup vs baseline: 1.4479x; 1.0133x over previous
#include <cuda_runtime.h>
#include <math.h>
#include <stdint.h>

#define D 32
#define NCOL 529          // 1 + 32 + 496
#define LOG2E 1.4426950408889634f
#define TRAIN_BLOCKS 592

// ---- scratch (no allocations allowed) ----
// g_acc is zero at first launch (static init); prep_kernel re-zeroes it after use so
// every graph replay sees zeros again.
__device__ float  g_acc[560];    // [0..527] upper-tri X^T X (incl diag), [528..559] column sums
__device__ float  g_stats[64];   // mean[32], inv_sd[32]
__device__ float4 g_pc[512];     // circulant order: entry k*32+lane = pair (lane,(lane+k+1)&31)

__device__ __forceinline__ int tri_idx(int i, int j) {   // i <= j, upper triangle incl diag
    return i * 32 - (i * (i - 1)) / 2 + (j - i);
}

__device__ __forceinline__ float ex2f(float v) {
    float r;
    asm("ex2.approx.ftz.f32 %0, %1;" : "=f"(r) : "f"(v));
    return r;
}

__device__ __forceinline__ uint32_t smem_u32(const void* p) {
    uint32_t a;
    asm("{ .reg .u64 t; cvta.to.shared.u64 t, %1; cvt.u32.u64 %0, t; }" : "=r"(a) : "l"(p));
    return a;
}

// ---------------- kernel 1: circulant-shuffle SYRK (r9/r15 proven version) -------------------
__global__ void __launch_bounds__(256) train_kernel(const float* __restrict__ X, int n_train) {
    __shared__ float sacc[560];
    const int tid  = threadIdx.x;
    const int lane = tid & 31;
    const int wg   = blockIdx.x * 8 + (tid >> 5);      // global warp id
    const int W    = gridDim.x * 8;

    for (int t = tid; t < 560; t += 256) sacc[t] = 0.0f;

    float acc[17];
#pragma unroll
    for (int k = 0; k < 17; k++) acc[k] = 0.0f;
    float asum = 0.0f;

    int row = wg;
    for (; row + 3 * W < n_train; row += 4 * W) {       // MLP=4 batched loads
        float v0 = X[(size_t)row * 32 + lane];
        float v1 = X[(size_t)(row + W) * 32 + lane];
        float v2 = X[(size_t)(row + 2 * W) * 32 + lane];
        float v3 = X[(size_t)(row + 3 * W) * 32 + lane];
        asum += (v0 + v1) + (v2 + v3);
#pragma unroll
        for (int k = 0; k < 17; k++) {
            int src = (lane + k) & 31;
            acc[k] = fmaf(v0, __shfl_sync(0xffffffffu, v0, src), acc[k]);
            acc[k] = fmaf(v1, __shfl_sync(0xffffffffu, v1, src), acc[k]);
            acc[k] = fmaf(v2, __shfl_sync(0xffffffffu, v2, src), acc[k]);
            acc[k] = fmaf(v3, __shfl_sync(0xffffffffu, v3, src), acc[k]);
        }
    }
    for (; row < n_train; row += W) {                   // warp-uniform tail
        float v = X[(size_t)row * 32 + lane];
        asum += v;
#pragma unroll
        for (int k = 0; k < 17; k++)
            acc[k] = fmaf(v, __shfl_sync(0xffffffffu, v, (lane + k) & 31), acc[k]);
    }
    __syncthreads();   // sacc zeroed before smem atomics

#pragma unroll
    for (int k = 0; k < 17; k++) {
        int i = lane, j = (lane + k) & 31;
        int lo = min(i, j), hi = max(i, j);
        if (k < 16 || lane < 16)                        // k=16 pairs duplicated across half-warps
            atomicAdd(&sacc[tri_idx(lo, hi)], acc[k]);
    }
    atomicAdd(&sacc[528 + lane], asum);
    __syncthreads();

    for (int t = tid; t < 560; t += 256)                // spread-address global atomics
        atomicAdd(&g_acc[t], sacc[t]);
}

// ---------------- kernel 2: stats + pair table; re-zeroes g_acc for the next replay ----------
__global__ void __launch_bounds__(512) prep_kernel(int n_train) {
    __shared__ float mean_s[32], isd_s[32];
    const int t   = threadIdx.x;
    const float fn = (float)n_train;

    if (t < 32) {
        float m   = g_acc[528 + t] / fn;
        float var = (g_acc[tri_idx(t, t)] - fn * m * m) / (fn - 1.0f);
        float isd = 1.0f / sqrtf(var);
        mean_s[t] = m;  isd_s[t] = isd;
        g_stats[t] = m; g_stats[32 + t] = isd;
    }
    __syncthreads();

    // circulant entry: k = t>>5 (offset d = k+1), lane = t&31 -> pair (lane, (lane+d)&31)
    int k = t >> 5, lane = t & 31, d = k + 1;
    int a = lane, b = (lane + d) & 31;
    int i = min(a, b), j = max(a, b);
    bool valid = (d < 16) || (lane < 16);    // d=16 second half duplicates

    float4 pc;
    if (valid) {
        float cij = (g_acc[tri_idx(i, j)] - fn * mean_s[i] * mean_s[j]) / (fn - 1.0f);
        float r   = cij * isd_s[i] * isd_s[j];
        float om  = 1.0f - r * r;
        float inv = 1.0f / om;
        pc.x = 0.5f * r * r * inv * LOG2E;      // A' (coeff of zi^2+zj^2, base 2)
        pc.y = -r * inv * LOG2E;                // B' (coeff of zi*zj, base 2)
        pc.z = 0.5f * log2f(om);                // D' = log2(sqrt(1-r^2))
        int p   = 31 * i - (i * (i - 1)) / 2 + (j - i - 1);   // combinations() pair index
        pc.w = __int_as_float(33 + p);          // output column
    } else {
        pc.x = pc.y = pc.z = 0.0f;
        pc.w = __int_as_float(-1);
    }
    g_pc[t] = pc;

    __syncthreads();                                    // all g_acc reads complete
    for (int s = t; s < 560; s += 512) g_acc[s] = 0.0f; // reset for the next graph replay
}

// ---------------- kernel 3: eval — r15 proven: LDG-broadcast table, smem stage, TMA store ----
__global__ void __launch_bounds__(128) eval_kernel(const float* __restrict__ x,
                                                   float* __restrict__ out, int n_eval) {
    __shared__ __align__(16) float buf[4 * 4 * NCOL];   // 4 warps x (4 points x 529)

    const int tid  = threadIdx.x;
    const int lane = tid & 31;
    const int w    = tid >> 5;
    const int p0   = (blockIdx.x * 4 + w) * 4;           // 4 points per warp
    if (p0 >= n_eval) return;                             // warp-uniform; no block syncs anywhere
    const int valid = min(4, n_eval - p0);

    float* wb = buf + w * (4 * NCOL);

    const float mean = __ldg(&g_stats[lane]);
    const float isd  = __ldg(&g_stats[32 + lane]);
    // clamp reads for (rare) tail points
    int i0 = p0, i1 = min(p0 + 1, n_eval - 1), i2 = min(p0 + 2, n_eval - 1), i3 = min(p0 + 3, n_eval - 1);
    float z0 = (x[(size_t)i0 * 32 + lane] - mean) * isd;
    float z1 = (x[(size_t)i1 * 32 + lane] - mean) * isd;
    float z2 = (x[(size_t)i2 * 32 + lane] - mean) * isd;
    float z3 = (x[(size_t)i3 * 32 + lane] - mean) * isd;
    float q0 = z0 * z0, q1 = z1 * z1, q2 = z2 * z2, q3 = z3 * z3;

    // ones: cols 0..32 for each point
    wb[lane] = 1.0f; wb[NCOL + lane] = 1.0f; wb[2 * NCOL + lane] = 1.0f; wb[3 * NCOL + lane] = 1.0f;
    if (lane == 0) {
        wb[32] = 1.0f; wb[NCOL + 32] = 1.0f; wb[2 * NCOL + 32] = 1.0f; wb[3 * NCOL + 32] = 1.0f;
    }

#pragma unroll
    for (int k = 0; k < 16; k++) {
        float4 c  = __ldg(&g_pc[k * 32 + lane]);         // L1-broadcast hit: warp-uniform k
        int   col = __float_as_int(c.w);                 // -1 = masked duplicate (d=16 upper half)
        int   src = (lane + k + 1) & 31;

        float zj0 = __shfl_sync(0xffffffffu, z0, src);
        float zj1 = __shfl_sync(0xffffffffu, z1, src);
        float zj2 = __shfl_sync(0xffffffffu, z2, src);
        float zj3 = __shfl_sync(0xffffffffu, z3, src);

        float v0 = ex2f(fmaf(c.x, fmaf(zj0, zj0, q0), fmaf(c.y, z0 * zj0, c.z)));
        float v1 = ex2f(fmaf(c.x, fmaf(zj1, zj1, q1), fmaf(c.y, z1 * zj1, c.z)));
        float v2 = ex2f(fmaf(c.x, fmaf(zj2, zj2, q2), fmaf(c.y, z2 * zj2, c.z)));
        float v3 = ex2f(fmaf(c.x, fmaf(zj3, zj3, q3), fmaf(c.y, z3 * zj3, c.z)));

        if (col >= 0) {
            wb[col]            = v0;
            wb[NCOL + col]     = v1;
            wb[2 * NCOL + col] = v2;
            wb[3 * NCOL + col] = v3;
        }
    }

    __syncwarp();

    if (valid == 4) {
        if (lane == 0) {
            asm volatile("fence.proxy.async.shared::cta;" ::: "memory");
            float* gdst = out + (size_t)p0 * NCOL;           // p0 % 4 == 0 -> 16B aligned
            uint32_t ssrc = smem_u32(wb);                    // 8464B block, 16B aligned
            asm volatile("cp.async.bulk.global.shared::cta.bulk_group [%0], [%1], %2;"
                         :: "l"(gdst), "r"(ssrc), "r"(4 * NCOL * 4) : "memory");
            asm volatile("cp.async.bulk.commit_group;" ::: "memory");
            asm volatile("cp.async.bulk.wait_group 0;" ::: "memory");
        }
    } else {
        int n = valid * NCOL;                                // rare tail: scalar copy
        for (int e = lane; e < n; e += 32)
            out[(size_t)p0 * NCOL + e] = wb[e];
    }
}

// ---------------- launcher ----------------
extern "C" void kernel_launch(void* const* d_in, const int* in_sizes, int n_in,
                              void* d_out, int out_size) {
    const float* X_train = (const float*)d_in[0];
    const float* x       = (const float*)d_in[1];
    float*       out     = (float*)d_out;

    int n_train = in_sizes[0] / D;
    int n_eval  = in_sizes[1] / D;

    train_kernel<<<TRAIN_BLOCKS, 256>>>(X_train, n_train);
    prep_kernel<<<1, 512>>>(n_train);

    int warps  = (n_eval + 3) / 4;            // 4 points per warp
    int blocks = (warps + 3) / 4;             // 4 warps per block
    eval_kernel<<<blocks, 128>>>(x, out, n_eval);
}

// round 17
// speedup vs baseline: 1.4991x; 1.0354x over previous
#include <cuda_runtime.h>
#include <math.h>
#include <stdint.h>

#define D 32
#define NCOL 529          // 1 + 32 + 496
#define LOG2E 1.4426950408889634f
#define TRAIN_BLOCKS 592

// ---- scratch (no allocations allowed) ----
// g_acc is zero at first launch (static init); prep_kernel re-zeroes it after use so
// every graph replay sees zeros again.
__device__ float  g_acc[560];    // [0..527] upper-tri X^T X (incl diag), [528..559] column sums
__device__ float  g_stats[64];   // mean[32], inv_sd[32]
__device__ float4 g_pc[512];     // circulant order: entry k*32+lane = pair (lane,(lane+k+1)&31)

__device__ __forceinline__ int tri_idx(int i, int j) {   // i <= j, upper triangle incl diag
    return i * 32 - (i * (i - 1)) / 2 + (j - i);
}

__device__ __forceinline__ float ex2f(float v) {
    float r;
    asm("ex2.approx.ftz.f32 %0, %1;" : "=f"(r) : "f"(v));
    return r;
}

__device__ __forceinline__ uint32_t smem_u32(const void* p) {
    uint32_t a;
    asm("{ .reg .u64 t; cvta.to.shared.u64 t, %1; cvt.u32.u64 %0, t; }" : "=r"(a) : "l"(p));
    return a;
}

// ---------------- kernel 1: circulant-shuffle SYRK; store+reduce epilogue (no smem atomics) --
__global__ void __launch_bounds__(256) train_kernel(const float* __restrict__ X, int n_train) {
    __shared__ float wsum[8][18][32];   // per-warp slab: [k=0..16] acc, [17] column sum
    const int tid  = threadIdx.x;
    const int lane = tid & 31;
    const int wl   = tid >> 5;                          // warp within block
    const int wg   = blockIdx.x * 8 + wl;               // global warp id
    const int W    = gridDim.x * 8;

    float acc[17];
#pragma unroll
    for (int k = 0; k < 17; k++) acc[k] = 0.0f;
    float asum = 0.0f;

    int row = wg;
    for (; row + 3 * W < n_train; row += 4 * W) {       // MLP=4 batched loads
        float v0 = X[(size_t)row * 32 + lane];
        float v1 = X[(size_t)(row + W) * 32 + lane];
        float v2 = X[(size_t)(row + 2 * W) * 32 + lane];
        float v3 = X[(size_t)(row + 3 * W) * 32 + lane];
        asum += (v0 + v1) + (v2 + v3);
#pragma unroll
        for (int k = 0; k < 17; k++) {
            int src = (lane + k) & 31;
            acc[k] = fmaf(v0, __shfl_sync(0xffffffffu, v0, src), acc[k]);
            acc[k] = fmaf(v1, __shfl_sync(0xffffffffu, v1, src), acc[k]);
            acc[k] = fmaf(v2, __shfl_sync(0xffffffffu, v2, src), acc[k]);
            acc[k] = fmaf(v3, __shfl_sync(0xffffffffu, v3, src), acc[k]);
        }
    }
    for (; row < n_train; row += W) {                   // warp-uniform tail
        float v = X[(size_t)row * 32 + lane];
        asum += v;
#pragma unroll
        for (int k = 0; k < 17; k++)
            acc[k] = fmaf(v, __shfl_sync(0xffffffffu, v, (lane + k) & 31), acc[k]);
    }

    // plain conflict-free stores to this warp's slab (no atomics)
#pragma unroll
    for (int k = 0; k < 17; k++) wsum[wl][k][lane] = acc[k];
    wsum[wl][17][lane] = asum;
    __syncthreads();

    // 560 slots: sum the 8 warps' values, one global atomic each.
    // tri entry (lo,hi), d = hi-lo: source is (k=d, lane=lo) if d<=16 else (k=32-d, lane=hi).
    for (int t = tid; t < 560; t += 256) {
        int k, ln;
        if (t < 528) {
            int lo = 0, rem = t;
            while (rem >= 32 - lo) { rem -= 32 - lo; lo++; }
            int hi = lo + rem;
            int d  = hi - lo;
            if (d <= 16) { k = d;      ln = lo; }
            else         { k = 32 - d; ln = hi; }
        } else {
            k = 17; ln = t - 528;
        }
        float s = 0.0f;
#pragma unroll
        for (int w = 0; w < 8; w++) s += wsum[w][k][ln];
        atomicAdd(&g_acc[t], s);
    }
}

// ---------------- kernel 2: stats + pair table; re-zeroes g_acc for the next replay ----------
__global__ void __launch_bounds__(512) prep_kernel(int n_train) {
    __shared__ float mean_s[32], isd_s[32];
    const int t   = threadIdx.x;
    const float fn = (float)n_train;

    if (t < 32) {
        float m   = g_acc[528 + t] / fn;
        float var = (g_acc[tri_idx(t, t)] - fn * m * m) / (fn - 1.0f);
        float isd = 1.0f / sqrtf(var);
        mean_s[t] = m;  isd_s[t] = isd;
        g_stats[t] = m; g_stats[32 + t] = isd;
    }
    __syncthreads();

    // circulant entry: k = t>>5 (offset d = k+1), lane = t&31 -> pair (lane, (lane+d)&31)
    int k = t >> 5, lane = t & 31, d = k + 1;
    int a = lane, b = (lane + d) & 31;
    int i = min(a, b), j = max(a, b);
    bool valid = (d < 16) || (lane < 16);    // d=16 second half duplicates

    float4 pc;
    if (valid) {
        float cij = (g_acc[tri_idx(i, j)] - fn * mean_s[i] * mean_s[j]) / (fn - 1.0f);
        float r   = cij * isd_s[i] * isd_s[j];
        float om  = 1.0f - r * r;
        float inv = 1.0f / om;
        pc.x = 0.5f * r * r * inv * LOG2E;      // A' (coeff of zi^2+zj^2, base 2)
        pc.y = -r * inv * LOG2E;                // B' (coeff of zi*zj, base 2)
        pc.z = 0.5f * log2f(om);                // D' = log2(sqrt(1-r^2))
        int p   = 31 * i - (i * (i - 1)) / 2 + (j - i - 1);   // combinations() pair index
        pc.w = __int_as_float(33 + p);          // output column
    } else {
        pc.x = pc.y = pc.z = 0.0f;
        pc.w = __int_as_float(-1);
    }
    g_pc[t] = pc;

    __syncthreads();                                    // all g_acc reads complete
    for (int s = t; s < 560; s += 512) g_acc[s] = 0.0f; // reset for the next graph replay
}

// ---------------- kernel 3: eval — r15 proven: LDG-broadcast table, smem stage, TMA store ----
__global__ void __launch_bounds__(128) eval_kernel(const float* __restrict__ x,
                                                   float* __restrict__ out, int n_eval) {
    __shared__ __align__(16) float buf[4 * 4 * NCOL];   // 4 warps x (4 points x 529)

    const int tid  = threadIdx.x;
    const int lane = tid & 31;
    const int w    = tid >> 5;
    const int p0   = (blockIdx.x * 4 + w) * 4;           // 4 points per warp
    if (p0 >= n_eval) return;                             // warp-uniform; no block syncs anywhere
    const int valid = min(4, n_eval - p0);

    float* wb = buf + w * (4 * NCOL);

    const float mean = __ldg(&g_stats[lane]);
    const float isd  = __ldg(&g_stats[32 + lane]);
    // clamp reads for (rare) tail points
    int i0 = p0, i1 = min(p0 + 1, n_eval - 1), i2 = min(p0 + 2, n_eval - 1), i3 = min(p0 + 3, n_eval - 1);
    float z0 = (x[(size_t)i0 * 32 + lane] - mean) * isd;
    float z1 = (x[(size_t)i1 * 32 + lane] - mean) * isd;
    float z2 = (x[(size_t)i2 * 32 + lane] - mean) * isd;
    float z3 = (x[(size_t)i3 * 32 + lane] - mean) * isd;
    float q0 = z0 * z0, q1 = z1 * z1, q2 = z2 * z2, q3 = z3 * z3;

    // ones: cols 0..32 for each point
    wb[lane] = 1.0f; wb[NCOL + lane] = 1.0f; wb[2 * NCOL + lane] = 1.0f; wb[3 * NCOL + lane] = 1.0f;
    if (lane == 0) {
        wb[32] = 1.0f; wb[NCOL + 32] = 1.0f; wb[2 * NCOL + 32] = 1.0f; wb[3 * NCOL + 32] = 1.0f;
    }

#pragma unroll
    for (int k = 0; k < 16; k++) {
        float4 c  = __ldg(&g_pc[k * 32 + lane]);         // L1-broadcast hit: warp-uniform k
        int   col = __float_as_int(c.w);                 // -1 = masked duplicate (d=16 upper half)
        int   src = (lane + k + 1) & 31;

        float zj0 = __shfl_sync(0xffffffffu, z0, src);
        float zj1 = __shfl_sync(0xffffffffu, z1, src);
        float zj2 = __shfl_sync(0xffffffffu, z2, src);
        float zj3 = __shfl_sync(0xffffffffu, z3, src);

        float v0 = ex2f(fmaf(c.x, fmaf(zj0, zj0, q0), fmaf(c.y, z0 * zj0, c.z)));
        float v1 = ex2f(fmaf(c.x, fmaf(zj1, zj1, q1), fmaf(c.y, z1 * zj1, c.z)));
        float v2 = ex2f(fmaf(c.x, fmaf(zj2, zj2, q2), fmaf(c.y, z2 * zj2, c.z)));
        float v3 = ex2f(fmaf(c.x, fmaf(zj3, zj3, q3), fmaf(c.y, z3 * zj3, c.z)));

        if (col >= 0) {
            wb[col]            = v0;
            wb[NCOL + col]     = v1;
            wb[2 * NCOL + col] = v2;
            wb[3 * NCOL + col] = v3;
        }
    }

    __syncwarp();

    if (valid == 4) {
        if (lane == 0) {
            asm volatile("fence.proxy.async.shared::cta;" ::: "memory");
            float* gdst = out + (size_t)p0 * NCOL;           // p0 % 4 == 0 -> 16B aligned
            uint32_t ssrc = smem_u32(wb);                    // 8464B block, 16B aligned
            asm volatile("cp.async.bulk.global.shared::cta.bulk_group [%0], [%1], %2;"
                         :: "l"(gdst), "r"(ssrc), "r"(4 * NCOL * 4) : "memory");
            asm volatile("cp.async.bulk.commit_group;" ::: "memory");
            asm volatile("cp.async.bulk.wait_group 0;" ::: "memory");
        }
    } else {
        int n = valid * NCOL;                                // rare tail: scalar copy
        for (int e = lane; e < n; e += 32)
            out[(size_t)p0 * NCOL + e] = wb[e];
    }
}

// ---------------- launcher ----------------
extern "C" void kernel_launch(void* const* d_in, const int* in_sizes, int n_in,
                              void* d_out, int out_size) {
    const float* X_train = (const float*)d_in[0];
    const float* x       = (const float*)d_in[1];
    float*       out     = (float*)d_out;

    int n_train = in_sizes[0] / D;
    int n_eval  = in_sizes[1] / D;

    train_kernel<<<TRAIN_BLOCKS, 256>>>(X_train, n_train);
    prep_kernel<<<1, 512>>>(n_train);

    int warps  = (n_eval + 3) / 4;            // 4 points per warp
    int blocks = (warps + 3) / 4;             // 4 warps per block
    eval_kernel<<<blocks, 128>>>(x, out, n_eval);
}